// round 13
// baseline (speedup 1.0000x reference)
#include <cuda_runtime.h>
#include <cuda_fp16.h>
#include <cstdint>
#include <float.h>
#include <math.h>

// Problem constants
#define B_    2
#define S_    2048
#define D_    2048
#define HQ_   16
#define HKV_  4
#define HD_   128
#define GQA_  (HQ_ / HKV_)      // 4
#define ROWS_ (B_ * S_)         // 4096
#define KVD_  (HKV_ * HD_)      // 512
#define QKVN_ 3072              // 2048 (Q) + 512 (K) + 512 (V)
#define ROPEN_ 2560             // cols < this get RoPE (Q and K)

// ---------------------------------------------------------------------------
// Scratch (no allocations allowed) — fp16 operand world
// ---------------------------------------------------------------------------
__device__ __half g_xh [(size_t)ROWS_ * D_];            // 16 MB
__device__ __half g_qkv[(size_t)ROWS_ * QKVN_];         // 24 MB  Q|K|V
__device__ __half g_vT [(size_t)B_ * HKV_ * HD_ * S_];  //  4 MB
__device__ __half g_oh [(size_t)ROWS_ * D_];            // 16 MB
__device__ __half g_wcT[(size_t)QKVN_ * D_];            // 12 MB
__device__ __half g_woT[(size_t)D_ * D_];               //  8 MB
__device__ __half g_sc [(size_t)B_ * HQ_ * S_ * S_];    // 256 MB exp-scores
__device__ float  g_bcat[QKVN_];
__device__ float  g_rowpart[(size_t)B_ * HQ_ * S_ * 16];
__device__ float  g_rowinv [(size_t)B_ * HQ_ * S_];

__device__ __forceinline__ uint32_t smem_u32(const void* p) {
    uint32_t a;
    asm("{ .reg .u64 t; cvta.to.shared.u64 t, %1; cvt.u32.u64 %0, t; }"
        : "=r"(a) : "l"(p));
    return a;
}

// mma.sync m16n8k16 f16 with f32 accumulate (arch-generic PTX)
#define MMA_F16(acc, af, bf) \
    asm volatile("mma.sync.aligned.m16n8k16.row.col.f32.f16.f16.f32 " \
                 "{%0,%1,%2,%3}, {%4,%5,%6,%7}, {%8,%9}, {%0,%1,%2,%3};" \
                 : "+f"((acc)[0]), "+f"((acc)[1]), "+f"((acc)[2]), "+f"((acc)[3]) \
                 : "r"((af)[0]), "r"((af)[1]), "r"((af)[2]), "r"((af)[3]), \
                   "r"((bf)[0]), "r"((bf)[1]))

#define CP16(dst, src) \
    asm volatile("cp.async.cg.shared.global [%0], [%1], 16;" :: "r"(dst), "l"(src))
#define CP_COMMIT() asm volatile("cp.async.commit_group;" ::: "memory")
#define CP_WAIT2()  asm volatile("cp.async.wait_group 2;"  ::: "memory")

// Swizzled smem, half world: stage = 128 rows x 32 halves (64 B/row).
// u32 unit (half2) index of (row, h2idx)
#define S32(P, r, h2) ((P)[((r) << 4) + ((((h2) >> 2) ^ (((r) >> 1) & 3)) << 2) + ((h2) & 3)])

// ---------------------------------------------------------------------------
// fp16 tensor GEMM: C = A[M,K] @ Bt[N,K]^T. Block 128x128, BK=32 halves,
// 128 thr / 4 warps, warp tile 64x64, 4-stage cp.async, swizzled smem.
// 3 CTAs/SM: B-fragments loaded just-in-time (1-deep pipeline) to fit regs.
// mode 0: plain, persistent over ntiles; optional fused RoPE; C half or f32.
// mode 1: scores: causal; zero tiles -> fp32 attn; epilogue exp -> half g_sc
//         + fp32 row partials.
// mode 2: attn@V: A = half exp scores, truncated K; in-loop normalized fp32
//         attn writeback; epilogue rows scaled by rowinv -> half oh.
// ---------------------------------------------------------------------------
__global__ __launch_bounds__(128, 3)
void mma_gemm(const __half* __restrict__ A, const __half* __restrict__ Bt,
              const float* __restrict__ bias,
              __half* __restrict__ Ch, float* __restrict__ Cf,
              int K, int lda, int ldb, int ldch, int ldcf,
              int mode, float scale,
              float* __restrict__ rowpart, const float* __restrict__ rowinv,
              const float* __restrict__ fc, const float* __restrict__ fs,
              int dorope, int halfC, int ntiles, int ntx)
{
    extern __shared__ uint32_t dsm[];  // A stages: st*2048 u32; B: +8192 u32

    int tid = threadIdx.x, lane = tid & 31, wid = tid >> 5;
    int g = lane >> 2, tg = lane & 3;
    int wm = (wid & 1) * 64;
    int wn = (wid >> 1) * 64;
    uint32_t sbase = smem_u32(dsm);
    int r0 = tid >> 2, kq = tid & 3;
    uint32_t d0 = (uint32_t)(r0 * 64 + ((kq ^ ((r0 >> 1) & 3)) * 16));

    int t_begin, t_step, t_count;
    if (mode == 0) { t_begin = blockIdx.x; t_step = gridDim.x; t_count = ntiles; }
    else           { t_begin = 0;          t_step = 1;         t_count = 1; }

    for (int t = t_begin; t < t_count; t += t_step) {
        int m0, n0, bh = blockIdx.z;
        const __half* Ap = A; const __half* Bp = Bt;
        __half* Chp = Ch; float* Cfp = Cf;
        int kmax = K;

        if (mode == 0) {
            m0 = (t / ntx) * 128;
            n0 = (t - (t / ntx) * ntx) * 128;
        } else if (mode == 1) {
            m0 = blockIdx.y * 128; n0 = blockIdx.x * 128;
            int b = bh >> 4, h = bh & 15;
            Chp = Ch + (size_t)bh * S_ * S_;
            Cfp = Cf + (size_t)bh * S_ * S_;
            if (n0 > m0) {                    // above diagonal: fp32 zeros
                float4 z = make_float4(0.f, 0.f, 0.f, 0.f);
                for (int i = tid; i < 128 * 32; i += 128) {
                    int row = i >> 5, q4 = i & 31;
                    *(float4*)&Cfp[(size_t)(m0 + row) * ldcf + n0 + q4 * 4] = z;
                }
                continue;
            }
            Ap = A  + (size_t)b * S_ * QKVN_ + h * HD_;
            Bp = Bt + (size_t)b * S_ * QKVN_ + 2048 + (h / GQA_) * HD_;
        } else {
            m0 = ((int)gridDim.y - 1 - (int)blockIdx.y) * 128;  // heavy first
            n0 = 0;
            int b = bh >> 4, h = bh & 15;
            Ap = A  + (size_t)bh * S_ * S_;
            Bp = Bt + (size_t)(b * HKV_ + h / GQA_) * HD_ * S_;
            Chp = Ch + (size_t)b * S_ * D_ + h * HD_;
            Cfp = Cf + (size_t)bh * S_ * S_;
            kmax = m0 + 128;                 // causal truncation
        }

        float acc[4][8][4];
        #pragma unroll
        for (int mt = 0; mt < 4; mt++)
            #pragma unroll
            for (int nt = 0; nt < 8; nt++)
                #pragma unroll
                for (int i = 0; i < 4; i++) acc[mt][nt][i] = 0.f;

        const __half* gA = Ap + (size_t)(m0 + r0) * lda + kq * 8;
        const __half* gB = Bp + (size_t)(n0 + r0) * ldb + kq * 8;
        size_t astep = (size_t)32 * lda, bstep = (size_t)32 * ldb;

        float invr[4];
        if (mode == 2) {
            const float* ri = rowinv + (size_t)bh * S_ + m0;
            #pragma unroll
            for (int j = 0; j < 4; j++) invr[j] = ri[r0 + 32 * j];
        }

#define ISSUE(kt) do {                                                    \
    uint32_t sa = sbase + ((kt) & 3) * 8192;                              \
    uint32_t sb = sa + 32768;                                             \
    size_t ko = (size_t)(kt) << 5;                                        \
    CP16(sa + d0,        gA + ko);                                        \
    CP16(sa + d0 + 2048, gA + ko + astep);                                \
    CP16(sa + d0 + 4096, gA + ko + 2 * astep);                            \
    CP16(sa + d0 + 6144, gA + ko + 3 * astep);                            \
    CP16(sb + d0,        gB + ko);                                        \
    CP16(sb + d0 + 2048, gB + ko + bstep);                                \
    CP16(sb + d0 + 4096, gB + ko + 2 * bstep);                            \
    CP16(sb + d0 + 6144, gB + ko + 3 * bstep);                            \
} while (0)

        int NT = kmax >> 5;                  // >= 4 always

        ISSUE(0); CP_COMMIT();
        ISSUE(1); CP_COMMIT();
        ISSUE(2); CP_COMMIT();

        for (int kt = 0; kt < NT; kt++) {
            CP_WAIT2();
            __syncthreads();
            if (kt + 3 < NT) ISSUE(kt + 3);
            CP_COMMIT();

            const uint32_t* As_ = dsm + (kt & 3) * 2048;
            const uint32_t* Bs_ = As_ + 8192;
            #pragma unroll
            for (int ks = 0; ks < 2; ks++) {
                int hb = ks * 8 + tg;
                uint32_t af[4][4];
                #pragma unroll
                for (int mt = 0; mt < 4; mt++) {
                    int r = wm + mt * 16 + g;
                    af[mt][0] = S32(As_, r,     hb);
                    af[mt][1] = S32(As_, r + 8, hb);
                    af[mt][2] = S32(As_, r,     hb + 4);
                    af[mt][3] = S32(As_, r + 8, hb + 4);
                }
                // B fragments just-in-time with 1-deep pipeline (reg relief)
                uint32_t b0 = S32(Bs_, wn + g, hb);
                uint32_t b1 = S32(Bs_, wn + g, hb + 4);
                #pragma unroll
                for (int nt = 0; nt < 8; nt++) {
                    uint32_t nb0 = 0, nb1 = 0;
                    if (nt < 7) {
                        int c = wn + (nt + 1) * 8 + g;
                        nb0 = S32(Bs_, c, hb);
                        nb1 = S32(Bs_, c, hb + 4);
                    }
                    uint32_t bfr[2] = { b0, b1 };
                    #pragma unroll
                    for (int mt = 0; mt < 4; mt++)
                        MMA_F16(acc[mt][nt], af[mt], bfr);
                    b0 = nb0; b1 = nb1;
                }
            }

            if (mode == 2) {
                // normalized fp32 attn writeback from this half A stage
                const uint32_t* As_w = dsm + (kt & 3) * 2048;
                #pragma unroll
                for (int j = 0; j < 4; j++) {
                    int rw = r0 + 32 * j;
                    int ib = rw * 16 + ((kq ^ ((rw >> 1) & 3)) << 2);
                    float iv = invr[j];
                    float2 f0 = __half22float2(*(const __half2*)&As_w[ib]);
                    float2 f1 = __half22float2(*(const __half2*)&As_w[ib + 1]);
                    float2 f2 = __half22float2(*(const __half2*)&As_w[ib + 2]);
                    float2 f3 = __half22float2(*(const __half2*)&As_w[ib + 3]);
                    float* dst = &Cfp[(size_t)(m0 + rw) * ldcf + (kt << 5) + kq * 8];
                    *(float4*)dst       = make_float4(f0.x * iv, f0.y * iv, f1.x * iv, f1.y * iv);
                    *(float4*)(dst + 4) = make_float4(f2.x * iv, f2.y * iv, f3.x * iv, f3.y * iv);
                }
            }
        }
#undef ISSUE

        // ---------------- Epilogues ----------------
        if (mode == 1) {
            float rs[4][2];
            #pragma unroll
            for (int mt = 0; mt < 4; mt++) { rs[mt][0] = 0.f; rs[mt][1] = 0.f; }

            #pragma unroll
            for (int mt = 0; mt < 4; mt++) {
                int r = m0 + wm + mt * 16 + g;
                #pragma unroll
                for (int nt = 0; nt < 8; nt++) {
                    int c = n0 + wn + nt * 8 + tg * 2;
                    float e00 = (c     <= r)     ? __expf(fminf(acc[mt][nt][0] * scale, 11.f)) : 0.f;
                    float e01 = (c + 1 <= r)     ? __expf(fminf(acc[mt][nt][1] * scale, 11.f)) : 0.f;
                    float e10 = (c     <= r + 8) ? __expf(fminf(acc[mt][nt][2] * scale, 11.f)) : 0.f;
                    float e11 = (c + 1 <= r + 8) ? __expf(fminf(acc[mt][nt][3] * scale, 11.f)) : 0.f;
                    __half2 h0 = __float22half2_rn(make_float2(e00, e01));
                    __half2 h1 = __float22half2_rn(make_float2(e10, e11));
                    *(__half2*)&Chp[(size_t)r * ldch + c]       = h0;
                    *(__half2*)&Chp[(size_t)(r + 8) * ldch + c] = h1;
                    float2 f0 = __half22float2(h0);   // sum the rounded values
                    float2 f1 = __half22float2(h1);
                    rs[mt][0] += f0.x + f0.y;
                    rs[mt][1] += f1.x + f1.y;
                }
                rs[mt][0] += __shfl_xor_sync(0xffffffffu, rs[mt][0], 1);
                rs[mt][0] += __shfl_xor_sync(0xffffffffu, rs[mt][0], 2);
                rs[mt][1] += __shfl_xor_sync(0xffffffffu, rs[mt][1], 1);
                rs[mt][1] += __shfl_xor_sync(0xffffffffu, rs[mt][1], 2);
            }
            __syncthreads();
            float* sums = (float*)dsm;       // [128][2]
            if (tg == 0) {
                #pragma unroll
                for (int mt = 0; mt < 4; mt++) {
                    sums[(wm + mt * 16 + g) * 2     + (wn >> 6)] = rs[mt][0];
                    sums[(wm + mt * 16 + g + 8) * 2 + (wn >> 6)] = rs[mt][1];
                }
            }
            __syncthreads();
            rowpart[(((size_t)bh * S_ + m0 + tid) << 4) + (n0 >> 7)]
                = sums[tid * 2] + sums[tid * 2 + 1];
            continue;
        }

        const float* rib = (mode == 2) ? (rowinv + (size_t)bh * S_) : nullptr;
        #pragma unroll
        for (int mt = 0; mt < 4; mt++) {
            int r = m0 + wm + mt * 16 + g;
            float s0 = 1.f, s1 = 1.f;
            if (mode == 2) { s0 = rib[r]; s1 = rib[r + 8]; }
            #pragma unroll
            for (int nt = 0; nt < 8; nt++) {
                int c = n0 + wn + nt * 8 + tg * 2;
                float v00 = acc[mt][nt][0] * s0;
                float v01 = acc[mt][nt][1] * s0;
                float v10 = acc[mt][nt][2] * s1;
                float v11 = acc[mt][nt][3] * s1;
                if (bias) {
                    float b0 = bias[c], b1 = bias[c + 1];
                    v00 += b0; v01 += b1; v10 += b0; v11 += b1;
                }
                if (dorope && c < ROPEN_) {   // fused RoPE (pairs c,c+1)
                    int i = (c & 127) >> 1;
                    int sr0 = r & (S_ - 1), sr1 = (r + 8) & (S_ - 1);
                    float c0 = fc[sr0 * 64 + i], sn0 = fs[sr0 * 64 + i];
                    float c1 = fc[sr1 * 64 + i], sn1 = fs[sr1 * 64 + i];
                    float t00 = v00 * c0 - v01 * sn0;
                    float t01 = v00 * sn0 + v01 * c0;
                    float t10 = v10 * c1 - v11 * sn1;
                    float t11 = v10 * sn1 + v11 * c1;
                    v00 = t00; v01 = t01; v10 = t10; v11 = t11;
                }
                if (halfC) {
                    *(__half2*)&Chp[(size_t)r * ldch + c]       = __float22half2_rn(make_float2(v00, v01));
                    *(__half2*)&Chp[(size_t)(r + 8) * ldch + c] = __float22half2_rn(make_float2(v10, v11));
                } else {
                    *(float2*)&Cfp[(size_t)r * ldcf + c]       = make_float2(v00, v01);
                    *(float2*)&Cfp[(size_t)(r + 8) * ldcf + c] = make_float2(v10, v11);
                }
            }
        }
        __syncthreads();   // protect smem stages before next persistent tile
    }
}

// ---------------------------------------------------------------------------
// Finalize 1/rowsum from per-tile partials (deterministic).
// ---------------------------------------------------------------------------
__global__ void rowinv_kernel(const float* __restrict__ rowpart,
                              float* __restrict__ rowinv)
{
    int i = blockIdx.x * 256 + threadIdx.x;
    if (i >= B_ * HQ_ * S_) return;
    int row = i & (S_ - 1);
    int nt = (row >> 7) + 1;
    const float* p = rowpart + ((size_t)i << 4);
    float s = 0.f;
    for (int t = 0; t < nt; t++) s += p[t];
    rowinv[i] = 1.f / s;
}

// ---------------------------------------------------------------------------
// Merged prep: x fp32->half, 4 weight transposes (fp32->half), bias concat.
// One launch; segments by blockIdx.x. 256 threads.
// ---------------------------------------------------------------------------
__global__ __launch_bounds__(256)
void prep_kernel(const float* __restrict__ x,
                 const float* __restrict__ wq, const float* __restrict__ wk,
                 const float* __restrict__ wv, const float* __restrict__ wo,
                 const float* __restrict__ bq, const float* __restrict__ bk,
                 const float* __restrict__ bv,
                 __half* __restrict__ xh, __half* __restrict__ wcT,
                 __half* __restrict__ woT, float* __restrict__ bct)
{
    __shared__ float t[32][33];
    const int NX = 8192;             // xconv: 2M float4 / 256
    const int NQ = 64 * 64, NK = 16 * 64, NV = 16 * 64, NO = 64 * 64;
    int bx = blockIdx.x;
    int tid = threadIdx.x;

    if (bx < NX) {                   // x conversion
        int i = bx * 256 + tid;
        float4 v = ((const float4*)x)[i];
        __half2* o = (__half2*)xh;
        o[2 * i]     = __float22half2_rn(make_float2(v.x, v.y));
        o[2 * i + 1] = __float22half2_rn(make_float2(v.z, v.w));
        return;
    }
    bx -= NX;

    const float* in; __half* out; int R, C;
    if (bx < NQ)                     { in = wq; out = wcT;                      R = D_; C = D_; }
    else if (bx < NQ + NK)           { bx -= NQ; in = wk; out = wcT + (size_t)2048 * D_; R = D_; C = KVD_; }
    else if (bx < NQ + NK + NV)      { bx -= NQ + NK; in = wv; out = wcT + (size_t)2560 * D_; R = D_; C = KVD_; }
    else if (bx < NQ + NK + NV + NO) { bx -= NQ + NK + NV; in = wo; out = woT;  R = D_; C = D_; }
    else {                           // bias concat
        bx -= NQ + NK + NV + NO;
        int i = bx * 256 + tid;
        if (i < QKVN_) {
            float v = (i < 2048) ? bq[i] : (i < 2560 ? bk[i - 2048] : bv[i - 2560]);
            bct[i] = v;
        }
        return;
    }

    int ncx = C / 32;
    int cx = bx % ncx, ry = bx / ncx;
    int c0 = cx * 32, r0 = ry * 32;
    int xx = tid & 31, yy = tid >> 5;
    #pragma unroll
    for (int i = 0; i < 32; i += 8) t[yy + i][xx] = in[(size_t)(r0 + yy + i) * C + c0 + xx];
    __syncthreads();
    #pragma unroll
    for (int i = 0; i < 32; i += 8) out[(size_t)(c0 + yy + i) * R + r0 + xx] = __float2half_rn(t[xx][yy + i]);
}

// ---------------------------------------------------------------------------
// V^T from fused QKV buffer (half -> half)
// ---------------------------------------------------------------------------
__global__ void vtrans_kernel(const __half* __restrict__ qkv, __half* __restrict__ vt)
{
    __shared__ __half t[32][33];
    int z = blockIdx.z; int b = z >> 2, h = z & 3;
    const __half* in = qkv + (size_t)b * S_ * QKVN_ + 2560 + h * HD_;
    __half* out = vt + (size_t)z * HD_ * S_;
    int s0 = blockIdx.y * 32, d0 = blockIdx.x * 32;
    int x = threadIdx.x, y = threadIdx.y;
    #pragma unroll
    for (int i = 0; i < 32; i += 8) t[y + i][x] = in[(size_t)(s0 + y + i) * QKVN_ + d0 + x];
    __syncthreads();
    #pragma unroll
    for (int i = 0; i < 32; i += 8) out[(size_t)(d0 + y + i) * S_ + s0 + x] = t[x][y + i];
}

// ---------------------------------------------------------------------------
extern "C" void kernel_launch(void* const* d_in, const int* in_sizes, int n_in,
                              void* d_out, int out_size)
{
    const float* x  = (const float*)d_in[0];
    const float* fc = (const float*)d_in[1];
    const float* fs = (const float*)d_in[2];
    const float* wq = (const float*)d_in[3];
    const float* bq = (const float*)d_in[4];
    const float* wk = (const float*)d_in[5];
    const float* bk = (const float*)d_in[6];
    const float* wv = (const float*)d_in[7];
    const float* bv = (const float*)d_in[8];
    const float* wo = (const float*)d_in[9];

    float* out  = (float*)d_out;
    float* attn = out + (size_t)B_ * S_ * D_;   // tuple order: (out, attn)

    __half *xh, *qkv, *vtb, *ohb, *wcT, *woT, *scb;
    float *bct, *rpb, *rib;
    cudaGetSymbolAddress((void**)&xh,  g_xh);
    cudaGetSymbolAddress((void**)&qkv, g_qkv);
    cudaGetSymbolAddress((void**)&vtb, g_vT);
    cudaGetSymbolAddress((void**)&ohb, g_oh);
    cudaGetSymbolAddress((void**)&wcT, g_wcT);
    cudaGetSymbolAddress((void**)&woT, g_woT);
    cudaGetSymbolAddress((void**)&scb, g_sc);
    cudaGetSymbolAddress((void**)&bct, g_bcat);
    cudaGetSymbolAddress((void**)&rpb, g_rowpart);
    cudaGetSymbolAddress((void**)&rib, g_rowinv);

    const int GSMEM = 65536;
    static int smem_set = 0;
    if (!smem_set) {
        cudaFuncSetAttribute(mma_gemm, cudaFuncAttributeMaxDynamicSharedMemorySize, GSMEM);
        smem_set = 1;
    }
    const int PGRID = 444;   // 3 CTAs/SM persistent

    // Prep (single launch): xconv + wq/wk/wv/wo transposes + bias concat
    {
        const int NPREP = 8192 + 64 * 64 + 16 * 64 + 16 * 64 + 64 * 64 + 12;
        prep_kernel<<<NPREP, 256>>>(x, wq, wk, wv, wo, bq, bk, bv, xh, wcT, woT, bct);
    }

    // Fused QKV projection + RoPE epilogue (persistent, half C)
    mma_gemm<<<PGRID, 128, GSMEM>>>(
        xh, wcT, bct, qkv, nullptr, D_, D_, D_, QKVN_, 0,
        0, 1.0f, nullptr, nullptr, fc, fs, 1, 1,
        (ROWS_ / 128) * (QKVN_ / 128), QKVN_ / 128);

    // V^T
    vtrans_kernel<<<dim3(HD_ / 32, S_ / 32, B_ * HKV_), dim3(32, 8)>>>(qkv, vtb);

    // Scores: exp(q.k*scale) causal -> half g_sc; fp32 zeros above diag; partials
    mma_gemm<<<dim3(S_ / 128, S_ / 128, B_ * HQ_), 128, GSMEM>>>(
        qkv, qkv, nullptr, scb, attn, HD_, QKVN_, QKVN_, S_, S_,
        1, 1.0f / sqrtf((float)D_), rpb, nullptr, nullptr, nullptr, 0, 0, 0, 0);

    // 1/rowsum
    rowinv_kernel<<<(B_ * HQ_ * S_ + 255) / 256, 256>>>(rpb, rib);

    // attn@V: half exp scores @ V^T; fp32 normalized attn writeback; half oh
    mma_gemm<<<dim3(1, S_ / 128, B_ * HQ_), 128, GSMEM>>>(
        scb, vtb, nullptr, ohb, attn, S_, S_, S_, D_, S_,
        2, 1.0f, nullptr, rib, nullptr, nullptr, 0, 1, 0, 0);

    // out = oh @ Wo (persistent, fp32 C)
    mma_gemm<<<PGRID, 128, GSMEM>>>(
        ohb, woT, nullptr, nullptr, out, D_, D_, D_, 0, D_,
        0, 1.0f, nullptr, nullptr, nullptr, nullptr, 0, 0,
        (ROWS_ / 128) * (D_ / 128), D_ / 128);
}